// round 7
// baseline (speedup 1.0000x reference)
#include <cuda_runtime.h>
#include <cstdint>

// message_pass: out = prelu(prelu([x_i|x_j|ea] @ W1 + b1, a) @ W2 + b2, a)
// E=500000 rows, d_in=144, HID=128, C=64. fp32 in/out, TF32 tensor-core math.

#define CDIM 64
#define DIN  144
#define HID  128
#define MT   64          // rows per tile
#define XSTR 148         // padded X stride (conflict-free A-frag reads)
#define HSTR 132         // padded H stride (conflict-free A-frag reads)

// shared memory layout (float units)
#define SZ_W1F (18*16*32*2)       // 18432: W1 fragment-packed (k-step, n-atom, lane, {b0,b1})
#define SZ_W2F (16*8*32*2)        // 8192
#define OFF_W1F 0
#define OFF_W2F (OFF_W1F + SZ_W1F)
#define OFF_B1  (OFF_W2F + SZ_W2F)
#define OFF_B2  (OFF_B1 + 128)
#define OFF_X   (OFF_B2 + 64)     // 26816 (byte offset 16B aligned)
#define SZ_XBUF (MT*XSTR)         // 9472
#define OFF_H   (OFF_X + 2*SZ_XBUF)
#define SMEM_FLOATS (OFF_H + MT*HSTR)   // 54208 floats = 216832 bytes

__device__ __forceinline__ uint32_t f2tf32(float x) {
    uint32_t r;
    asm("cvt.rna.tf32.f32 %0, %1;" : "=r"(r) : "f"(x));
    return r;
}

__device__ __forceinline__ void mma_tf32(float* d, const uint32_t* a,
                                         uint32_t b0, uint32_t b1) {
    asm volatile(
        "mma.sync.aligned.m16n8k8.row.col.f32.tf32.tf32.f32 "
        "{%0,%1,%2,%3}, {%4,%5,%6,%7}, {%8,%9}, {%0,%1,%2,%3};"
        : "+f"(d[0]), "+f"(d[1]), "+f"(d[2]), "+f"(d[3])
        : "r"(a[0]), "r"(a[1]), "r"(a[2]), "r"(a[3]), "r"(b0), "r"(b1));
}

__device__ __forceinline__ void cp_async16(float* smem_dst, const float* gsrc, int src_bytes) {
    uint32_t saddr = (uint32_t)__cvta_generic_to_shared(smem_dst);
    asm volatile("cp.async.cg.shared.global [%0], [%1], 16, %2;"
                 :: "r"(saddr), "l"(gsrc), "r"(src_bytes));
}

__device__ __forceinline__ void prefetch_tile(
    float* sm, const float* __restrict__ xi, const float* __restrict__ xj,
    const float* __restrict__ ea, int tile, int bsel, int tid, int nrows)
{
    float* dst0 = sm + OFF_X + bsel * SZ_XBUF;
    #pragma unroll
    for (int j = 0; j < 9; ++j) {
        int v   = tid + 256 * j;          // 9*256 = 2304 = 64 rows * 36 float4
        int row = v / 36;
        int col = (v % 36) * 4;
        int grow = tile * MT + row;
        int nb   = (grow < nrows) ? 16 : 0;
        int gr   = grow < nrows ? grow : (nrows - 1);
        const float* src;
        if (col < 64)        src = xi + gr * 64 + col;
        else if (col < 128)  src = xj + gr * 64 + (col - 64);
        else                 src = ea + gr * 16 + (col - 128);
        cp_async16(dst0 + row * XSTR + col, src, nb);
    }
}

__global__ __launch_bounds__(256, 1)
void message_pass_22548578304895_kernel(
    const float* __restrict__ xi, const float* __restrict__ xj,
    const float* __restrict__ ea, const float* __restrict__ W1g,
    const float* __restrict__ b1g, const float* __restrict__ W2g,
    const float* __restrict__ b2g, const float* __restrict__ alphap,
    float* __restrict__ out, int nrows, int ntiles)
{
    extern __shared__ float sm[];
    const int tid  = threadIdx.x;
    const int w    = tid >> 5;
    const int lane = tid & 31;
    const int g    = lane >> 2;   // group id 0..7
    const int tig  = lane & 3;    // thread-in-group 0..3
    const float alpha = __ldg(alphap);

    // ---------------- weights: coalesced load -> fragment-packed permute ----------------
    {
        float* raw = sm + OFF_X;   // reuse X double-buffer as temp (18944 >= 18432)
        const float4* src1 = (const float4*)W1g;
        #pragma unroll
        for (int i = 0; i < 18; ++i)
            ((float4*)raw)[tid + 256 * i] = src1[tid + 256 * i];   // 18432 floats exact
        if (tid < 128) sm[OFF_B1 + tid] = b1g[tid];
        if (tid < 64)  sm[OFF_B2 + tid] = b2g[tid];
        __syncthreads();

        // W1 fragments: pair p = k*16 + atom; b0 = W1[8k+tig][8a+g], b1 = W1[8k+tig+4][8a+g]
        for (int p = w; p < 288; p += 8) {
            int k = p >> 4, ag = p & 15;
            float v0 = raw[(8 * k + tig) * 128 + 8 * ag + g];
            float v1 = raw[(8 * k + tig + 4) * 128 + 8 * ag + g];
            float2 d;
            d.x = __uint_as_float(f2tf32(v0));
            d.y = __uint_as_float(f2tf32(v1));
            *(float2*)(sm + OFF_W1F + (p * 32 + lane) * 2) = d;
        }
        __syncthreads();

        const float4* src2 = (const float4*)W2g;
        #pragma unroll
        for (int i = 0; i < 8; ++i)
            ((float4*)raw)[tid + 256 * i] = src2[tid + 256 * i];   // 8192 floats exact
        __syncthreads();

        for (int p = w; p < 128; p += 8) {
            int k = p >> 3, ag = p & 7;
            float v0 = raw[(8 * k + tig) * 64 + 8 * ag + g];
            float v1 = raw[(8 * k + tig + 4) * 64 + 8 * ag + g];
            float2 d;
            d.x = __uint_as_float(f2tf32(v0));
            d.y = __uint_as_float(f2tf32(v1));
            *(float2*)(sm + OFF_W2F + (p * 32 + lane) * 2) = d;
        }
        __syncthreads();
    }

    // warp tiling
    const int ni1 = w >> 1;            // layer1: 4 col-quarters (32 cols each)
    const int rb1 = (w & 1) * 32;      // layer1: 2 row-halves  (32 rows each)
    const int ni2 = w >> 2;            // layer2: 2 col-halves  (32 cols each)
    const int rb2 = (w & 3) * 16;      // layer2: 4 row-slabs   (16 rows each)

    int buf = 0;
    if ((int)blockIdx.x < ntiles)
        prefetch_tile(sm, xi, xj, ea, blockIdx.x, 0, tid, nrows);
    asm volatile("cp.async.commit_group;");

    for (int tile = blockIdx.x; tile < ntiles; tile += gridDim.x) {
        int nxt = tile + gridDim.x;
        if (nxt < ntiles)
            prefetch_tile(sm, xi, xj, ea, nxt, buf ^ 1, tid, nrows);
        asm volatile("cp.async.commit_group;");
        asm volatile("cp.async.wait_group 1;");
        __syncthreads();   // sX[buf] ready; prev tile's sH reads complete

        const float* Xb = sm + OFF_X + buf * SZ_XBUF;

        // ---------------- layer 1: [64,144] @ [144,128] ----------------
        float acc1[2][4][4];
        #pragma unroll
        for (int s = 0; s < 2; ++s)
            #pragma unroll
            for (int at = 0; at < 4; ++at)
                #pragma unroll
                for (int r = 0; r < 4; ++r) acc1[s][at][r] = 0.f;

        #pragma unroll
        for (int k = 0; k < 18; ++k) {
            uint32_t a[2][4];
            #pragma unroll
            for (int s = 0; s < 2; ++s) {
                const float* xr = Xb + (rb1 + s * 16 + g) * XSTR + k * 8 + tig;
                a[s][0] = f2tf32(xr[0]);
                a[s][2] = f2tf32(xr[4]);
                a[s][1] = f2tf32(xr[8 * XSTR]);
                a[s][3] = f2tf32(xr[8 * XSTR + 4]);
            }
            #pragma unroll
            for (int at = 0; at < 4; ++at) {
                int ag = ni1 * 4 + at;
                float2 bb = *(const float2*)(sm + OFF_W1F + ((k * 16 + ag) * 32 + lane) * 2);
                uint32_t b0 = __float_as_uint(bb.x), b1 = __float_as_uint(bb.y);
                mma_tf32(acc1[0][at], a[0], b0, b1);
                mma_tf32(acc1[1][at], a[1], b0, b1);
            }
        }

        // epilogue 1: bias + prelu + rna(tf32) -> sH
        #pragma unroll
        for (int s = 0; s < 2; ++s) {
            #pragma unroll
            for (int at = 0; at < 4; ++at) {
                int col = (ni1 * 4 + at) * 8 + 2 * tig;
                float bx = sm[OFF_B1 + col], by = sm[OFF_B1 + col + 1];
                #pragma unroll
                for (int pr = 0; pr < 2; ++pr) {
                    int row = rb1 + s * 16 + g + pr * 8;
                    float v0 = acc1[s][at][pr * 2 + 0] + bx;
                    float v1 = acc1[s][at][pr * 2 + 1] + by;
                    v0 = (v0 >= 0.f) ? v0 : alpha * v0;
                    v1 = (v1 >= 0.f) ? v1 : alpha * v1;
                    float2 st;
                    st.x = __uint_as_float(f2tf32(v0));
                    st.y = __uint_as_float(f2tf32(v1));
                    *(float2*)(sm + OFF_H + row * HSTR + col) = st;
                }
            }
        }
        __syncthreads();   // sH complete

        // ---------------- layer 2: [64,128] @ [128,64] ----------------
        float acc2[4][4];
        #pragma unroll
        for (int at = 0; at < 4; ++at)
            #pragma unroll
            for (int r = 0; r < 4; ++r) acc2[at][r] = 0.f;

        #pragma unroll
        for (int k = 0; k < 16; ++k) {
            uint32_t a[4];
            const float* hr = sm + OFF_H + (rb2 + g) * HSTR + k * 8 + tig;
            a[0] = __float_as_uint(hr[0]);
            a[2] = __float_as_uint(hr[4]);
            a[1] = __float_as_uint(hr[8 * HSTR]);
            a[3] = __float_as_uint(hr[8 * HSTR + 4]);
            #pragma unroll
            for (int at = 0; at < 4; ++at) {
                int ag = ni2 * 4 + at;
                float2 bb = *(const float2*)(sm + OFF_W2F + ((k * 8 + ag) * 32 + lane) * 2);
                mma_tf32(acc2[at], a, __float_as_uint(bb.x), __float_as_uint(bb.y));
            }
        }

        // epilogue 2: bias + prelu -> gmem (float2, coalesced 32B segments)
        #pragma unroll
        for (int at = 0; at < 4; ++at) {
            int col = (ni2 * 4 + at) * 8 + 2 * tig;
            float bx = sm[OFF_B2 + col], by = sm[OFF_B2 + col + 1];
            #pragma unroll
            for (int pr = 0; pr < 2; ++pr) {
                int row  = rb2 + g + pr * 8;
                int grow = tile * MT + row;
                float v0 = acc2[at][pr * 2 + 0] + bx;
                float v1 = acc2[at][pr * 2 + 1] + by;
                v0 = (v0 >= 0.f) ? v0 : alpha * v0;
                v1 = (v1 >= 0.f) ? v1 : alpha * v1;
                if (grow < nrows)
                    *(float2*)(out + (size_t)grow * 64 + col) = make_float2(v0, v1);
            }
        }

        buf ^= 1;
    }
}

extern "C" void kernel_launch(void* const* d_in, const int* in_sizes, int n_in,
                              void* d_out, int out_size) {
    const float* xi     = (const float*)d_in[0];
    const float* xj     = (const float*)d_in[1];
    const float* ea     = (const float*)d_in[2];
    const float* W1     = (const float*)d_in[3];
    const float* b1     = (const float*)d_in[4];
    const float* W2     = (const float*)d_in[5];
    const float* b2     = (const float*)d_in[6];
    const float* alphap = (const float*)d_in[7];
    float* out = (float*)d_out;

    int nrows  = in_sizes[0] / CDIM;              // E*H
    int ntiles = (nrows + MT - 1) / MT;

    int dev = 0, sms = 148;
    cudaGetDevice(&dev);
    cudaDeviceGetAttribute(&sms, cudaDevAttrMultiProcessorCount, dev);

    size_t smem = (size_t)SMEM_FLOATS * sizeof(float);   // 216832 B
    cudaFuncSetAttribute(message_pass_22548578304895_kernel,
                         cudaFuncAttributeMaxDynamicSharedMemorySize, (int)smem);

    int grid = sms < ntiles ? sms : ntiles;
    message_pass_22548578304895_kernel<<<grid, 256, smem>>>(
        xi, xj, ea, W1, b1, W2, b2, alphap, out, nrows, ntiles);
}

// round 8
// speedup vs baseline: 1.0051x; 1.0051x over previous
#include <cuda_runtime.h>
#include <cstdint>

// message_pass: out = prelu(prelu([x_i|x_j|ea] @ W1 + b1, a) @ W2 + b2, a)
// E=500000 rows, d_in=144, HID=128, C=64. fp32 in/out, TF32 tensor-core math.

#define CDIM 64
#define DIN  144
#define HID  128
#define MT   64          // rows per tile
#define XSTR 148         // padded X stride (conflict-free A-frag reads)
#define HSTR 132         // padded H stride (conflict-free A-frag reads)

// shared memory layout (float units)
#define SZ_W1F (18*16*32*2)       // 18432: W1 fragment-packed (k-step, n-atom, lane, {b0,b1})
#define SZ_W2F (16*8*32*2)        // 8192
#define OFF_W1F 0
#define OFF_W2F (OFF_W1F + SZ_W1F)
#define OFF_B1  (OFF_W2F + SZ_W2F)
#define OFF_B2  (OFF_B1 + 128)
#define OFF_X   (OFF_B2 + 64)     // 26816 (byte offset 16B aligned)
#define SZ_XBUF (MT*XSTR)         // 9472
#define OFF_H   (OFF_X + 2*SZ_XBUF)
#define SMEM_FLOATS (OFF_H + MT*HSTR)   // 54208 floats = 216832 bytes

__device__ __forceinline__ uint32_t f2tf32(float x) {
    uint32_t r;
    asm("cvt.rna.tf32.f32 %0, %1;" : "=r"(r) : "f"(x));
    return r;
}

__device__ __forceinline__ void mma_tf32(float* d, const uint32_t* a,
                                         uint32_t b0, uint32_t b1) {
    asm volatile(
        "mma.sync.aligned.m16n8k8.row.col.f32.tf32.tf32.f32 "
        "{%0,%1,%2,%3}, {%4,%5,%6,%7}, {%8,%9}, {%0,%1,%2,%3};"
        : "+f"(d[0]), "+f"(d[1]), "+f"(d[2]), "+f"(d[3])
        : "r"(a[0]), "r"(a[1]), "r"(a[2]), "r"(a[3]), "r"(b0), "r"(b1));
}

__device__ __forceinline__ void cp_async16(float* smem_dst, const float* gsrc, int src_bytes) {
    uint32_t saddr = (uint32_t)__cvta_generic_to_shared(smem_dst);
    asm volatile("cp.async.cg.shared.global [%0], [%1], 16, %2;"
                 :: "r"(saddr), "l"(gsrc), "r"(src_bytes));
}

__device__ __forceinline__ void prefetch_tile(
    float* sm, const float* __restrict__ xi, const float* __restrict__ xj,
    const float* __restrict__ ea, int tile, int bsel, int tid, int nrows)
{
    float* dst0 = sm + OFF_X + bsel * SZ_XBUF;
    #pragma unroll
    for (int j = 0; j < 9; ++j) {
        int v   = tid + 256 * j;          // 9*256 = 2304 = 64 rows * 36 float4
        int row = v / 36;
        int col = (v % 36) * 4;
        int grow = tile * MT + row;
        int nb   = (grow < nrows) ? 16 : 0;
        int gr   = grow < nrows ? grow : (nrows - 1);
        const float* src;
        if (col < 64)        src = xi + gr * 64 + col;
        else if (col < 128)  src = xj + gr * 64 + (col - 64);
        else                 src = ea + gr * 16 + (col - 128);
        cp_async16(dst0 + row * XSTR + col, src, nb);
    }
}

__global__ __launch_bounds__(256, 1)
void message_pass_22548578304895_kernel(
    const float* __restrict__ xi, const float* __restrict__ xj,
    const float* __restrict__ ea, const float* __restrict__ W1g,
    const float* __restrict__ b1g, const float* __restrict__ W2g,
    const float* __restrict__ b2g, const float* __restrict__ alphap,
    float* __restrict__ out, int nrows, int ntiles)
{
    extern __shared__ float sm[];
    const int tid  = threadIdx.x;
    const int w    = tid >> 5;
    const int lane = tid & 31;
    const int g    = lane >> 2;   // group id 0..7
    const int tig  = lane & 3;    // thread-in-group 0..3
    const float alpha = __ldg(alphap);

    // ---------------- weights: coalesced load -> fragment-packed permute ----------------
    {
        float* raw = sm + OFF_X;   // reuse X double-buffer as temp (18944 >= 18432)
        const float4* src1 = (const float4*)W1g;
        #pragma unroll
        for (int i = 0; i < 18; ++i)
            ((float4*)raw)[tid + 256 * i] = src1[tid + 256 * i];   // 18432 floats exact
        if (tid < 128) sm[OFF_B1 + tid] = b1g[tid];
        if (tid < 64)  sm[OFF_B2 + tid] = b2g[tid];
        __syncthreads();

        // W1 fragments: pair p = k*16 + atom; b0 = W1[8k+tig][8a+g], b1 = W1[8k+tig+4][8a+g]
        for (int p = w; p < 288; p += 8) {
            int k = p >> 4, ag = p & 15;
            float v0 = raw[(8 * k + tig) * 128 + 8 * ag + g];
            float v1 = raw[(8 * k + tig + 4) * 128 + 8 * ag + g];
            float2 d;
            d.x = __uint_as_float(f2tf32(v0));
            d.y = __uint_as_float(f2tf32(v1));
            *(float2*)(sm + OFF_W1F + (p * 32 + lane) * 2) = d;
        }
        __syncthreads();

        const float4* src2 = (const float4*)W2g;
        #pragma unroll
        for (int i = 0; i < 8; ++i)
            ((float4*)raw)[tid + 256 * i] = src2[tid + 256 * i];   // 8192 floats exact
        __syncthreads();

        for (int p = w; p < 128; p += 8) {
            int k = p >> 3, ag = p & 7;
            float v0 = raw[(8 * k + tig) * 64 + 8 * ag + g];
            float v1 = raw[(8 * k + tig + 4) * 64 + 8 * ag + g];
            float2 d;
            d.x = __uint_as_float(f2tf32(v0));
            d.y = __uint_as_float(f2tf32(v1));
            *(float2*)(sm + OFF_W2F + (p * 32 + lane) * 2) = d;
        }
        __syncthreads();
    }

    // warp tiling
    const int ni1 = w >> 1;            // layer1: 4 col-quarters (32 cols each)
    const int rb1 = (w & 1) * 32;      // layer1: 2 row-halves  (32 rows each)
    const int ni2 = w >> 2;            // layer2: 2 col-halves  (32 cols each)
    const int rb2 = (w & 3) * 16;      // layer2: 4 row-slabs   (16 rows each)

    int buf = 0;
    if ((int)blockIdx.x < ntiles)
        prefetch_tile(sm, xi, xj, ea, blockIdx.x, 0, tid, nrows);
    asm volatile("cp.async.commit_group;");

    for (int tile = blockIdx.x; tile < ntiles; tile += gridDim.x) {
        int nxt = tile + gridDim.x;
        if (nxt < ntiles)
            prefetch_tile(sm, xi, xj, ea, nxt, buf ^ 1, tid, nrows);
        asm volatile("cp.async.commit_group;");
        asm volatile("cp.async.wait_group 1;");
        __syncthreads();   // sX[buf] ready; prev tile's sH reads complete

        const float* Xb = sm + OFF_X + buf * SZ_XBUF;

        // ---------------- layer 1: [64,144] @ [144,128] ----------------
        float acc1[2][4][4];
        #pragma unroll
        for (int s = 0; s < 2; ++s)
            #pragma unroll
            for (int at = 0; at < 4; ++at)
                #pragma unroll
                for (int r = 0; r < 4; ++r) acc1[s][at][r] = 0.f;

        #pragma unroll
        for (int k = 0; k < 18; ++k) {
            uint32_t a[2][4];
            #pragma unroll
            for (int s = 0; s < 2; ++s) {
                const float* xr = Xb + (rb1 + s * 16 + g) * XSTR + k * 8 + tig;
                a[s][0] = f2tf32(xr[0]);
                a[s][2] = f2tf32(xr[4]);
                a[s][1] = f2tf32(xr[8 * XSTR]);
                a[s][3] = f2tf32(xr[8 * XSTR + 4]);
            }
            #pragma unroll
            for (int at = 0; at < 4; ++at) {
                int ag = ni1 * 4 + at;
                float2 bb = *(const float2*)(sm + OFF_W1F + ((k * 16 + ag) * 32 + lane) * 2);
                uint32_t b0 = __float_as_uint(bb.x), b1 = __float_as_uint(bb.y);
                mma_tf32(acc1[0][at], a[0], b0, b1);
                mma_tf32(acc1[1][at], a[1], b0, b1);
            }
        }

        // epilogue 1: bias + prelu + rna(tf32) -> sH
        #pragma unroll
        for (int s = 0; s < 2; ++s) {
            #pragma unroll
            for (int at = 0; at < 4; ++at) {
                int col = (ni1 * 4 + at) * 8 + 2 * tig;
                float bx = sm[OFF_B1 + col], by = sm[OFF_B1 + col + 1];
                #pragma unroll
                for (int pr = 0; pr < 2; ++pr) {
                    int row = rb1 + s * 16 + g + pr * 8;
                    float v0 = acc1[s][at][pr * 2 + 0] + bx;
                    float v1 = acc1[s][at][pr * 2 + 1] + by;
                    v0 = (v0 >= 0.f) ? v0 : alpha * v0;
                    v1 = (v1 >= 0.f) ? v1 : alpha * v1;
                    float2 st;
                    st.x = __uint_as_float(f2tf32(v0));
                    st.y = __uint_as_float(f2tf32(v1));
                    *(float2*)(sm + OFF_H + row * HSTR + col) = st;
                }
            }
        }
        __syncthreads();   // sH complete

        // ---------------- layer 2: [64,128] @ [128,64] ----------------
        float acc2[4][4];
        #pragma unroll
        for (int at = 0; at < 4; ++at)
            #pragma unroll
            for (int r = 0; r < 4; ++r) acc2[at][r] = 0.f;

        #pragma unroll
        for (int k = 0; k < 16; ++k) {
            uint32_t a[4];
            const float* hr = sm + OFF_H + (rb2 + g) * HSTR + k * 8 + tig;
            a[0] = __float_as_uint(hr[0]);
            a[2] = __float_as_uint(hr[4]);
            a[1] = __float_as_uint(hr[8 * HSTR]);
            a[3] = __float_as_uint(hr[8 * HSTR + 4]);
            #pragma unroll
            for (int at = 0; at < 4; ++at) {
                int ag = ni2 * 4 + at;
                float2 bb = *(const float2*)(sm + OFF_W2F + ((k * 8 + ag) * 32 + lane) * 2);
                mma_tf32(acc2[at], a, __float_as_uint(bb.x), __float_as_uint(bb.y));
            }
        }

        // epilogue 2: bias + prelu -> gmem (float2, coalesced 32B segments)
        #pragma unroll
        for (int at = 0; at < 4; ++at) {
            int col = (ni2 * 4 + at) * 8 + 2 * tig;
            float bx = sm[OFF_B2 + col], by = sm[OFF_B2 + col + 1];
            #pragma unroll
            for (int pr = 0; pr < 2; ++pr) {
                int row  = rb2 + g + pr * 8;
                int grow = tile * MT + row;
                float v0 = acc2[at][pr * 2 + 0] + bx;
                float v1 = acc2[at][pr * 2 + 1] + by;
                v0 = (v0 >= 0.f) ? v0 : alpha * v0;
                v1 = (v1 >= 0.f) ? v1 : alpha * v1;
                if (grow < nrows)
                    *(float2*)(out + (size_t)grow * 64 + col) = make_float2(v0, v1);
            }
        }

        buf ^= 1;
    }
}

extern "C" void kernel_launch(void* const* d_in, const int* in_sizes, int n_in,
                              void* d_out, int out_size) {
    const float* xi     = (const float*)d_in[0];
    const float* xj     = (const float*)d_in[1];
    const float* ea     = (const float*)d_in[2];
    const float* W1     = (const float*)d_in[3];
    const float* b1     = (const float*)d_in[4];
    const float* W2     = (const float*)d_in[5];
    const float* b2     = (const float*)d_in[6];
    const float* alphap = (const float*)d_in[7];
    float* out = (float*)d_out;

    int nrows  = in_sizes[0] / CDIM;              // E*H
    int ntiles = (nrows + MT - 1) / MT;

    int dev = 0, sms = 148;
    cudaGetDevice(&dev);
    cudaDeviceGetAttribute(&sms, cudaDevAttrMultiProcessorCount, dev);

    size_t smem = (size_t)SMEM_FLOATS * sizeof(float);   // 216832 B
    cudaFuncSetAttribute(message_pass_22548578304895_kernel,
                         cudaFuncAttributeMaxDynamicSharedMemorySize, (int)smem);

    int grid = sms < ntiles ? sms : ntiles;
    message_pass_22548578304895_kernel<<<grid, 256, smem>>>(
        xi, xj, ea, W1, b1, W2, b2, alphap, out, nrows, ntiles);
}